// round 10
// baseline (speedup 1.0000x reference)
#include <cuda_runtime.h>
#include <cuda_fp16.h>
#include <math.h>
#include <stdint.h>

#define D 4096
#define BB 512
#define N3 (3*D)
// kind::f16, fp16 inputs, fp32 accum, M=128, N=128
#define IDESC_F16 ((1u<<4)|(16u<<17)|(8u<<24))

#if defined(__CUDA_ARCH_FEAT_SM103_ALL) || defined(__CUDA_ARCH_FEAT_SM100_ALL) || \
    defined(__CUDA_ARCH_FEAT_SM101_ALL) || \
    (defined(__CUDA_ARCH_SPECIFIC__) && (__CUDA_ARCH_SPECIFIC__ >= 1000)) || \
    (defined(__CUDA_ARCH_FAMILY_SPECIFIC__) && (__CUDA_ARCH_FAMILY_SPECIFIC__ >= 1000))
#define TC_OK 1
#else
#define TC_OK 0
#endif

// ---------------- device scratch ----------------
__device__ __half g_pa[BB*D], g_x[BB*D], g_h[BB*D];
__device__ __half g_p1[(size_t)D*D];
__device__ __half g_p2[(size_t)N3*D];          // channel-permuted rows: c*D+j <- 3j+c
__device__ float  g_p2b[N3];
__device__ __half g_asT[(size_t)D*BB], g_arsT[(size_t)D*BB];
__device__ __half g_maT[(size_t)D*BB];
__device__ __half g_WnT_h[(size_t)D*D], g_WnT_l[(size_t)D*D];
__device__ __half g_WrT_h[(size_t)D*D], g_WrT_l[(size_t)D*D];
__device__ float g_nt[(size_t)BB*N3];
__device__ float g_rec[BB*D], g_recin[BB*D], g_act[BB*D];
__device__ float g_gsum[D], g_sdec[D], g_rmW[D], g_rsW[D], g_rmR[D], g_rsR[D];
__device__ float g_mPA[BB], g_sPA[BB], g_mPR[BB], g_sPR[BB];

// ---------------- helpers ----------------
__device__ __forceinline__ uint32_t s2u(const void* p) {
    uint32_t a;
    asm("{ .reg .u64 t; cvta.to.shared.u64 t, %1; cvt.u32.u64 %0, t; }" : "=r"(a) : "l"(p));
    return a;
}
__device__ __forceinline__ uint32_t sw128(uint32_t o) { return o ^ ((o >> 3) & 0x70); }
__device__ __forceinline__ void split2h(float v, __half& h, __half& l) {
    h = __float2half_rn(v);
    l = __float2half_rn(v - __half2float(h));
}
__device__ __forceinline__ float sigm(float x) { return 1.f / (1.f + expf(-x)); }

#if TC_OK
__device__ __forceinline__ void cp16(uint32_t d, const void* g) {
    asm volatile("cp.async.cg.shared.global [%0], [%1], 16;" :: "r"(d), "l"(g));
}
template<int N> __device__ __forceinline__ void cp_wait() {
    asm volatile("cp.async.wait_group %0;" :: "n"(N) : "memory");
}
__device__ __forceinline__ void cp_wait_n(int n) {
    switch (n) {
        case 0: cp_wait<0>(); break; case 1: cp_wait<1>(); break;
        case 2: cp_wait<2>(); break; case 3: cp_wait<3>(); break;
        default: cp_wait<4>(); break;
    }
}
__device__ __forceinline__ uint64_t sdesc(uint32_t a) {
    return 0x4000404000010000ull | ((uint64_t)(a >> 4) & 0x3FFFull);
}
__device__ __forceinline__ void mma_f16(uint32_t d, uint64_t ad, uint64_t bd, uint32_t en) {
    asm volatile(
        "{\n\t.reg .pred p;\n\t"
        "setp.ne.u32 p, %5, 0;\n\t"
        "tcgen05.mma.cta_group::1.kind::f16 [%0], %1, %2, %3, {%4, %4, %4, %4}, p;\n\t}"
        :: "r"(d), "l"(ad), "l"(bd), "r"(IDESC_F16), "r"(0u), "r"(en) : "memory");
}
__device__ __forceinline__ void mma_commit(uint32_t mb) {
    asm volatile("tcgen05.commit.cta_group::1.mbarrier::arrive::one.shared::cluster.b64 [%0];"
                 :: "r"(mb) : "memory");
}
__device__ __forceinline__ void mbar_init(uint32_t mb, uint32_t cnt) {
    asm volatile("mbarrier.init.shared.b64 [%0], %1;" :: "r"(mb), "r"(cnt) : "memory");
}
__device__ __forceinline__ void mbar_wait(uint32_t mb, uint32_t par) {
    asm volatile(
        "{\n\t.reg .pred P;\nW%=:\n\t"
        "mbarrier.try_wait.parity.shared.b64 P, [%0], %1;\n\t"
        "@!P bra W%=;\n\t}"
        :: "r"(mb), "r"(par) : "memory");
}
__device__ __forceinline__ void ldtm32(uint32_t* r, uint32_t a) {
    asm volatile(
        "tcgen05.ld.sync.aligned.32x32b.x32.b32 "
        "{%0,%1,%2,%3,%4,%5,%6,%7,%8,%9,%10,%11,%12,%13,%14,%15,"
        "%16,%17,%18,%19,%20,%21,%22,%23,%24,%25,%26,%27,%28,%29,%30,%31}, [%32];"
        : "=r"(r[0]),"=r"(r[1]),"=r"(r[2]),"=r"(r[3]),"=r"(r[4]),"=r"(r[5]),"=r"(r[6]),"=r"(r[7]),
          "=r"(r[8]),"=r"(r[9]),"=r"(r[10]),"=r"(r[11]),"=r"(r[12]),"=r"(r[13]),"=r"(r[14]),"=r"(r[15]),
          "=r"(r[16]),"=r"(r[17]),"=r"(r[18]),"=r"(r[19]),"=r"(r[20]),"=r"(r[21]),"=r"(r[22]),"=r"(r[23]),
          "=r"(r[24]),"=r"(r[25]),"=r"(r[26]),"=r"(r[27]),"=r"(r[28]),"=r"(r[29]),"=r"(r[30]),"=r"(r[31])
        : "r"(a));
}
#endif

// ---------------- GEMM: C[m,n] = sum_k A[m,k]*B[n,k]; A fp16; B = NBL fp16 panels ----------------
// 2 CTAs/SM (96KB smem each) so copies/syncs of one CTA overlap MMAs of the other.
// EPI: 0 fp32; 1 +bias relu -> fp16; 2 +bias fp32; 3 +addmat relu fp32; 4 Hebbian -> transposed hi/lo
template<int EPI, int NBL, int NST>
__global__ void __launch_bounds__(256)
mma_gemm(const __half* __restrict__ A,
         const __half* __restrict__ Bh, const __half* __restrict__ Bl,
         int K, int ldC, float* __restrict__ C,
         const float* __restrict__ bias, const float* __restrict__ addmat,
         const float* __restrict__ Wold, const float* __restrict__ rmax,
         const float* __restrict__ rsum, const float* __restrict__ sdec,
         __half* __restrict__ Oh, __half* __restrict__ Ol) {
    extern __shared__ char dsm[];
    const int tid = threadIdx.x;
    const int m0 = blockIdx.x * 128, n0 = blockIdx.y * 128;
    constexpr int NP = 1 + NBL;
    constexpr int STAGE = NP * 16384;
    constexpr int L = NST - 1;

#if TC_OK
    __shared__ uint32_t s_tm;
    __shared__ __align__(8) uint64_t s_mb[NST];
    const int wid = tid >> 5, lid = tid & 31;
    uint32_t tile0 = (s2u(dsm) + 1023u) & ~1023u;
    uint32_t mbA[NST];
#pragma unroll
    for (int s = 0; s < NST; s++) mbA[s] = s2u(&s_mb[s]);

    if (wid == 0) {
        asm volatile("tcgen05.alloc.cta_group::1.sync.aligned.shared::cta.b32 [%0], %1;"
                     :: "r"(s2u(&s_tm)), "r"(128u) : "memory");
        asm volatile("tcgen05.relinquish_alloc_permit.cta_group::1.sync.aligned;");
    }
    if (tid == 0)
        for (int s = 0; s < NST; s++) mbar_init(mbA[s], 1);
    __syncthreads();
    const uint32_t tm = s_tm;

    const __half* srcs[3] = { A + (size_t)m0 * K, Bh + (size_t)n0 * K,
                              NBL == 2 ? Bl + (size_t)n0 * K : nullptr };

    const int NC = K >> 6;

#define DO_COPY(i)                                                              \
    do {                                                                        \
        uint32_t base_ = tile0 + ((i) % NST) * STAGE;                           \
        _Pragma("unroll")                                                       \
        for (int p = 0; p < NP; p++) {                                          \
            const __half* s_ = srcs[p] + (i) * 64;                              \
            uint32_t pb_ = base_ + p * 16384;                                   \
            _Pragma("unroll")                                                   \
            for (int t = 0; t < 4; t++) {                                       \
                int idx_ = tid + t * 256;                                       \
                int r_ = idx_ >> 3, c_ = idx_ & 7;                              \
                cp16(pb_ + sw128(r_ * 128 + c_ * 16), s_ + (size_t)r_ * K + c_ * 8); \
            }                                                                   \
        }                                                                       \
        asm volatile("cp.async.commit_group;" ::: "memory");                    \
    } while (0)

    for (int c = 0; c < L && c < NC; c++) DO_COPY(c);

    for (int i = 0; i < NC; i++) {
        if (i + L < NC) {
            if (i >= 1) mbar_wait(mbA[(i - 1) % NST], ((i - 1) / NST) & 1);
            DO_COPY(i + L);
        }
        int rem = NC - 1 - i; if (rem > L) rem = L;
        cp_wait_n(rem);
        __syncthreads();
        if (tid == 0) {
            asm volatile("fence.proxy.async.shared::cta;" ::: "memory");
            uint32_t base = tile0 + (i % NST) * STAGE;
            uint64_t ad = sdesc(base);
            uint64_t bh = sdesc(base + 16384);
            uint64_t bl = sdesc(base + 32768);
#pragma unroll
            for (int s4 = 0; s4 < 4; s4++) {
                mma_f16(tm, ad + 2*s4, bh + 2*s4, (i > 0) | (s4 > 0));
                if (NBL == 2) mma_f16(tm, ad + 2*s4, bl + 2*s4, 1);
            }
            mma_commit(mbA[i % NST]);
        }
    }
#undef DO_COPY

    for (int j = (NC >= NST ? NC - NST : 0); j < NC; j++)
        mbar_wait(mbA[j % NST], (j / NST) & 1);
    asm volatile("tcgen05.fence::after_thread_sync;" ::: "memory");

    if (wid < 4) {
        const int m = m0 + wid * 32 + lid;
        float sd = 0.f, rm = 0.f, irs = 1.f;
        if (EPI == 4) { sd = sdec[m]; rm = rmax[m]; irs = 1.f / rsum[m]; }
#pragma unroll
        for (int cb = 0; cb < 4; cb++) {
            uint32_t rr[32];
            ldtm32(rr, tm + cb * 32);
            asm volatile("tcgen05.wait::ld.sync.aligned;" ::: "memory");
            const int nb = n0 + cb * 32;
            if (EPI == 0) {
                float4* c4 = (float4*)(C + (size_t)m * ldC + nb);
#pragma unroll
                for (int q = 0; q < 8; q++)
                    c4[q] = make_float4(__uint_as_float(rr[4*q]), __uint_as_float(rr[4*q+1]),
                                        __uint_as_float(rr[4*q+2]), __uint_as_float(rr[4*q+3]));
            } else if (EPI == 1) {
#pragma unroll
                for (int j = 0; j < 32; j += 2) {
                    float v0 = fmaxf(__uint_as_float(rr[j])   + bias[nb+j],   0.f);
                    float v1 = fmaxf(__uint_as_float(rr[j+1]) + bias[nb+j+1], 0.f);
                    *(__half2*)(Oh + (size_t)m * ldC + nb + j) = __floats2half2_rn(v0, v1);
                }
            } else if (EPI == 2) {
                float4* c4 = (float4*)(C + (size_t)m * ldC + nb);
#pragma unroll
                for (int q = 0; q < 8; q++)
                    c4[q] = make_float4(__uint_as_float(rr[4*q])   + bias[nb+4*q],
                                        __uint_as_float(rr[4*q+1]) + bias[nb+4*q+1],
                                        __uint_as_float(rr[4*q+2]) + bias[nb+4*q+2],
                                        __uint_as_float(rr[4*q+3]) + bias[nb+4*q+3]);
            } else if (EPI == 3) {
                const float4* a4 = (const float4*)(addmat + (size_t)m * ldC + nb);
                float4* c4 = (float4*)(C + (size_t)m * ldC + nb);
#pragma unroll
                for (int q = 0; q < 8; q++) {
                    float4 a = a4[q];
                    c4[q] = make_float4(fmaxf(__uint_as_float(rr[4*q])   + a.x, 0.f),
                                        fmaxf(__uint_as_float(rr[4*q+1]) + a.y, 0.f),
                                        fmaxf(__uint_as_float(rr[4*q+2]) + a.z, 0.f),
                                        fmaxf(__uint_as_float(rr[4*q+3]) + a.w, 0.f));
                }
            } else {
                const float4* w4 = (const float4*)(Wold + (size_t)m * D + nb);
#pragma unroll
                for (int q = 0; q < 8; q++) {
                    float4 w = w4[q];
                    float wv[4] = { w.x, w.y, w.z, w.w };
#pragma unroll
                    for (int e = 0; e < 4; e++) {
                        int j = 4*q + e;
                        float p = expf(wv[e] - rm) * irs;
                        float o = wv[e] + p * (__uint_as_float(rr[j]) * (1.0f/BB)) - sd * wv[e];
                        __half hh, ll;
                        split2h(o, hh, ll);
                        Oh[(size_t)(nb + j) * D + m] = hh;
                        Ol[(size_t)(nb + j) * D + m] = ll;
                    }
                }
            }
        }
    }
    __syncthreads();
    if (wid == 0)
        asm volatile("tcgen05.dealloc.cta_group::1.sync.aligned.b32 %0, %1;" :: "r"(tm), "r"(128u));

#else  // ---------- generic-target fallback ----------
    float* As = (float*)dsm;
    float* Bs = As + 16 * 132;
    const int tx = tid & 15, ty = tid >> 4;
    float acc[8][8];
#pragma unroll
    for (int i = 0; i < 8; i++)
#pragma unroll
        for (int j = 0; j < 8; j++) acc[i][j] = 0.f;
    for (int k0 = 0; k0 < K; k0 += 16) {
#pragma unroll
        for (int e = 0; e < 8; e++) {
            int idx = tid + e * 256;
            int r = idx >> 4, k = idx & 15;
            size_t ai = (size_t)(m0 + r) * K + k0 + k;
            size_t bi = (size_t)(n0 + r) * K + k0 + k;
            As[k * 132 + r] = __half2float(A[ai]);
            float bv = __half2float(Bh[bi]);
            if (NBL == 2) bv += __half2float(Bl[bi]);
            Bs[k * 132 + r] = bv;
        }
        __syncthreads();
#pragma unroll
        for (int kk = 0; kk < 16; kk++) {
            float a[8], b[8];
#pragma unroll
            for (int i = 0; i < 8; i++) a[i] = As[kk * 132 + ty * 8 + i];
#pragma unroll
            for (int j = 0; j < 8; j++) b[j] = Bs[kk * 132 + tx * 8 + j];
#pragma unroll
            for (int i = 0; i < 8; i++)
#pragma unroll
                for (int j = 0; j < 8; j++) acc[i][j] = fmaf(a[i], b[j], acc[i][j]);
        }
        __syncthreads();
    }
#pragma unroll
    for (int i = 0; i < 8; i++) {
        int m = m0 + ty * 8 + i;
        float sd = 0.f, rm = 0.f, irs = 1.f;
        if (EPI == 4) { sd = sdec[m]; rm = rmax[m]; irs = 1.f / rsum[m]; }
#pragma unroll
        for (int j = 0; j < 8; j++) {
            int n = n0 + tx * 8 + j;
            float v = acc[i][j];
            if (EPI == 0) C[(size_t)m * ldC + n] = v;
            else if (EPI == 1) Oh[(size_t)m * ldC + n] = __float2half_rn(fmaxf(v + bias[n], 0.f));
            else if (EPI == 2) C[(size_t)m * ldC + n] = v + bias[n];
            else if (EPI == 3) C[(size_t)m * ldC + n] = fmaxf(v + addmat[(size_t)m * ldC + n], 0.f);
            else {
                float w = Wold[(size_t)m * D + n];
                float p = expf(w - rm) * irs;
                float o = w + p * (v * (1.0f/BB)) - sd * w;
                __half hh, ll; split2h(o, hh, ll);
                Oh[(size_t)n * D + m] = hh; Ol[(size_t)n * D + m] = ll;
            }
        }
    }
#endif
}

// ---------------- block reduce + elementwise ----------------
__device__ __forceinline__ float blk_reduce(float v, bool do_max) {
    __shared__ float sh[32];
    int lane = threadIdx.x & 31, w = threadIdx.x >> 5;
#pragma unroll
    for (int o = 16; o; o >>= 1) {
        float t = __shfl_xor_sync(0xffffffffu, v, o);
        v = do_max ? fmaxf(v, t) : v + t;
    }
    if (lane == 0) sh[w] = v;
    __syncthreads();
    if (w == 0) {
        v = (lane < (int)(blockDim.x >> 5)) ? sh[lane] : (do_max ? -INFINITY : 0.f);
#pragma unroll
        for (int o = 16; o; o >>= 1) {
            float t = __shfl_xor_sync(0xffffffffu, v, o);
            v = do_max ? fmaxf(v, t) : v + t;
        }
        if (lane == 0) sh[0] = v;
    }
    __syncthreads();
    float r = sh[0];
    __syncthreads();
    return r;
}

__global__ void row_stats_kernel(const float* __restrict__ src,
                                 float* __restrict__ rmax, float* __restrict__ rsum) {
    int row = blockIdx.x;
    const float* x = src + (size_t)row * D;
    float m = -INFINITY;
    for (int i = threadIdx.x; i < D; i += blockDim.x) m = fmaxf(m, x[i]);
    m = blk_reduce(m, true);
    float s = 0.f;
    for (int i = threadIdx.x; i < D; i += blockDim.x) s += expf(x[i] - m);
    s = blk_reduce(s, false);
    if (threadIdx.x == 0) { rmax[row] = m; rsum[row] = s; }
}

__global__ void softmax_tn_kernel(const float* __restrict__ src,
                                  const float* __restrict__ rm, const float* __restrict__ rs,
                                  __half* __restrict__ dst) {
    __shared__ float tile[32][33];
    __shared__ float tm[32], ts[32];
    int i0 = blockIdx.x * 32, b0 = blockIdx.y * 32;
    int tx = threadIdx.x & 31, ty = threadIdx.x >> 5;
    if (threadIdx.x < 32) { tm[threadIdx.x] = rm[b0 + threadIdx.x]; ts[threadIdx.x] = 1.f / rs[b0 + threadIdx.x]; }
    __syncthreads();
#pragma unroll
    for (int r = ty; r < 32; r += 8)
        tile[r][tx] = src[(size_t)(b0 + r) * D + i0 + tx];
    __syncthreads();
#pragma unroll
    for (int r = ty; r < 32; r += 8)
        dst[(size_t)(i0 + r) * BB + b0 + tx] = __float2half_rn(expf(tile[tx][r] - tm[tx]) * ts[tx]);
}

__global__ void layernorm_kernel(const float* __restrict__ src,
                                 const float* __restrict__ g, const float* __restrict__ b,
                                 float* __restrict__ dst) {
    int row = blockIdx.x;
    const float* x = src + (size_t)row * D;
    float s = 0.f, s2 = 0.f;
    for (int i = threadIdx.x; i < D; i += blockDim.x) { float v = x[i]; s += v; s2 += v * v; }
    s = blk_reduce(s, false);
    s2 = blk_reduce(s2, false);
    float mean = s * (1.f / D);
    float rstd = rsqrtf(s2 * (1.f / D) - mean * mean + 1e-5f);
    for (int i = threadIdx.x; i < D; i += blockDim.x)
        dst[(size_t)row * D + i] = (x[i] - mean) * rstd * g[i] + b[i];
}

__global__ void zero_kernel(float* p, int n) {
    int i = blockIdx.x * blockDim.x + threadIdx.x;
    if (i < n) p[i] = 0.f;
}

__global__ void neuromod_t(const float* __restrict__ nt,
                           const float* __restrict__ dopamine,
                           const float* __restrict__ serotonin,
                           const float* __restrict__ gaba,
                           const float* __restrict__ alpha,
                           __half* __restrict__ maT, float* __restrict__ gsum) {
    __shared__ float tile[64][33];
    int j0 = blockIdx.x * 32, b0 = blockIdx.y * 64;
    int tx = threadIdx.x & 31, ty = threadIdx.x >> 5;
    int j = j0 + tx;
    float a = alpha[j];
    float gs = 0.f;
    for (int bb = ty; bb < 64; bb += 8) {
        int b = b0 + bb;
        const float* p = nt + (size_t)b * N3;
        float pd = p[j], ps = p[D + j], pg = p[2*D + j];
        float inv = 1.f / fmaxf(ps, 1e-6f);
        size_t bi = (size_t)b * D + j;
        float dop = tanhf(dopamine[bi] + pd * inv);
        float ser = sigm(serotonin[bi] + ps);
        gs += sigm(gaba[bi] + pg * inv);
        tile[bb][tx] = a * dop * ser;
    }
    atomicAdd(&gsum[j], gs);
    __syncthreads();
    int c = threadIdx.x & 63, jy = threadIdx.x >> 6;
#pragma unroll
    for (int jj = jy; jj < 32; jj += 4)
        maT[(size_t)(j0 + jj) * BB + b0 + c] = __float2half_rn(tile[c][jj]);
}

__global__ void sdecay_kernel(const float* __restrict__ gsum,
                              const float* __restrict__ decay, float* __restrict__ sdec) {
    int j = blockIdx.x * blockDim.x + threadIdx.x;
    sdec[j] = decay[j] * sigm(gsum[j] * (1.f / BB));
}

__global__ void cvt_kernel(const float4* __restrict__ src, __half* __restrict__ dst, size_t n4) {
    size_t i = (size_t)blockIdx.x * blockDim.x + threadIdx.x;
    if (i >= n4) return;
    float4 v = src[i];
    ((__half2*)dst)[2*i]   = __floats2half2_rn(v.x, v.y);
    ((__half2*)dst)[2*i+1] = __floats2half2_rn(v.z, v.w);
}

__global__ void cvt_permute_kernel(const float* __restrict__ src, __half* __restrict__ dst) {
    int r = blockIdx.x;
    int c = r % 3, j = r / 3;
    const float4* s4 = (const float4*)(src + (size_t)r * D);
    __half2* d2 = (__half2*)(dst + (size_t)(c * D + j) * D);
    for (int i = threadIdx.x; i < D / 4; i += blockDim.x) {
        float4 v = s4[i];
        d2[2*i]   = __floats2half2_rn(v.x, v.y);
        d2[2*i+1] = __floats2half2_rn(v.z, v.w);
    }
}

__global__ void permute_bias_kernel(const float* __restrict__ src, float* __restrict__ dst) {
    int r = blockIdx.x * blockDim.x + threadIdx.x;
    if (r < N3) dst[(r % 3) * D + r / 3] = src[r];
}

// ---------------- host ----------------
template<typename T>
static void* sym_addr(T& sym) { void* p = nullptr; cudaGetSymbolAddress(&p, sym); return p; }
#define HF(sym) ((__half*)sym_addr(sym))
#define FP(sym) ((float*)sym_addr(sym))

extern "C" void kernel_launch(void* const* d_in, const int* in_sizes, int n_in,
                              void* d_out, int out_size) {
    const float* x        = (const float*)d_in[0];
    const float* prev_act = (const float*)d_in[1];
    const float* prev_rec = (const float*)d_in[2];
    const float* dopamine = (const float*)d_in[3];
    const float* serotonin= (const float*)d_in[4];
    const float* gaba     = (const float*)d_in[5];
    const float* W        = (const float*)d_in[6];
    const float* Wr       = (const float*)d_in[7];
    const float* alpha    = (const float*)d_in[8];
    const float* decay    = (const float*)d_in[9];
    const float* gact     = (const float*)d_in[10];
    const float* bact     = (const float*)d_in[11];
    const float* grec     = (const float*)d_in[12];
    const float* brec     = (const float*)d_in[13];
    const float* p1w      = (const float*)d_in[14];
    const float* p1b      = (const float*)d_in[15];
    const float* p2w      = (const float*)d_in[16];
    const float* p2b      = (const float*)d_in[17];
    float* out = (float*)d_out;

    // 2 CTAs/SM: 96KB stages + slack
    const int SM1 = 3 * 32768 + 1024;   // NBL=1, NST=3
    const int SM2 = 2 * 49152 + 1024;   // NBL=2, NST=2

    static cudaStream_t s1, s2;
    static cudaEvent_t ev_root, ev_pa, ev_as, ev_p2, ev_sw, ev_ma, ev_wn, ev_ri;
    static bool init_done = false;
    if (!init_done) {
        cudaStreamCreateWithFlags(&s1, cudaStreamNonBlocking);
        cudaStreamCreateWithFlags(&s2, cudaStreamNonBlocking);
        cudaEventCreateWithFlags(&ev_root, cudaEventDisableTiming);
        cudaEventCreateWithFlags(&ev_pa, cudaEventDisableTiming);
        cudaEventCreateWithFlags(&ev_as, cudaEventDisableTiming);
        cudaEventCreateWithFlags(&ev_p2, cudaEventDisableTiming);
        cudaEventCreateWithFlags(&ev_sw, cudaEventDisableTiming);
        cudaEventCreateWithFlags(&ev_ma, cudaEventDisableTiming);
        cudaEventCreateWithFlags(&ev_wn, cudaEventDisableTiming);
        cudaEventCreateWithFlags(&ev_ri, cudaEventDisableTiming);
        cudaFuncSetAttribute((const void*)mma_gemm<1,1,3>, cudaFuncAttributeMaxDynamicSharedMemorySize, SM1);
        cudaFuncSetAttribute((const void*)mma_gemm<2,1,3>, cudaFuncAttributeMaxDynamicSharedMemorySize, SM1);
        cudaFuncSetAttribute((const void*)mma_gemm<4,1,3>, cudaFuncAttributeMaxDynamicSharedMemorySize, SM1);
        cudaFuncSetAttribute((const void*)mma_gemm<0,2,2>, cudaFuncAttributeMaxDynamicSharedMemorySize, SM2);
        cudaFuncSetAttribute((const void*)mma_gemm<3,2,2>, cudaFuncAttributeMaxDynamicSharedMemorySize, SM2);
        init_done = true;
    }

    // ---- FORK: side streams join capture via origin-stream event FIRST ----
    cudaEventRecord(ev_root, 0);
    cudaStreamWaitEvent(s1, ev_root, 0);
    cudaStreamWaitEvent(s2, ev_root, 0);

    // ---- s0: input converts ----
    cvt_kernel<<<(BB*D/4 + 255)/256, 256>>>((const float4*)prev_act, HF(g_pa), BB*D/4);
    cvt_kernel<<<(BB*D/4 + 255)/256, 256>>>((const float4*)x,        HF(g_x),  BB*D/4);
    cudaEventRecord(ev_pa, 0);

    // ---- s1: p1 convert -> GEMM1 ----
    cvt_kernel<<<((size_t)D*D/4 + 255)/256, 256, 0, s1>>>((const float4*)p1w, HF(g_p1), (size_t)D*D/4);
    cudaStreamWaitEvent(s1, ev_pa, 0);
    mma_gemm<1,1,3><<<dim3(BB/128, D/128), 256, SM1, s1>>>(
        HF(g_pa), HF(g_p1), nullptr, D, D,
        nullptr, p1b, nullptr, nullptr, nullptr, nullptr, nullptr, HF(g_h), nullptr);

    // ---- s2: p2 convert + W row stats ----
    cvt_permute_kernel<<<N3, 256, 0, s2>>>(p2w, HF(g_p2));
    permute_bias_kernel<<<(N3 + 255)/256, 256, 0, s2>>>(p2b, FP(g_p2b));
    cudaEventRecord(ev_p2, s2);
    row_stats_kernel<<<D, 256, 0, s2>>>(W,  FP(g_rmW), FP(g_rsW));
    cudaEventRecord(ev_sw, s2);
    row_stats_kernel<<<D, 256, 0, s2>>>(Wr, FP(g_rmR), FP(g_rsR));

    // ---- s0: transposed softmaxes ----
    row_stats_kernel<<<BB, 256>>>(prev_act, FP(g_mPA), FP(g_sPA));
    softmax_tn_kernel<<<dim3(D/32, BB/32), 256>>>(prev_act, FP(g_mPA), FP(g_sPA), HF(g_asT));
    row_stats_kernel<<<BB, 256>>>(prev_rec, FP(g_mPR), FP(g_sPR));
    softmax_tn_kernel<<<dim3(D/32, BB/32), 256>>>(prev_rec, FP(g_mPR), FP(g_sPR), HF(g_arsT));
    cudaEventRecord(ev_as, 0);

    // ---- s1: GEMM2 + neuromod + Hebbian-W ----
    cudaStreamWaitEvent(s1, ev_p2, 0);
    mma_gemm<2,1,3><<<dim3(BB/128, N3/128), 256, SM1, s1>>>(
        HF(g_h), HF(g_p2), nullptr, D, N3,
        FP(g_nt), FP(g_p2b), nullptr, nullptr, nullptr, nullptr, nullptr, nullptr, nullptr);
    zero_kernel<<<D/256, 256, 0, s1>>>(FP(g_gsum), D);
    neuromod_t<<<dim3(D/32, BB/64), 256, 0, s1>>>(FP(g_nt), dopamine, serotonin, gaba, alpha,
                                                  HF(g_maT), FP(g_gsum));
    sdecay_kernel<<<D/256, 256, 0, s1>>>(FP(g_gsum), decay, FP(g_sdec));
    cudaEventRecord(ev_ma, s1);
    cudaStreamWaitEvent(s1, ev_as, 0);
    cudaStreamWaitEvent(s1, ev_sw, 0);
    mma_gemm<4,1,3><<<dim3(D/128, D/128), 256, SM1, s1>>>(
        HF(g_asT), HF(g_maT), nullptr, BB, D,
        nullptr, nullptr, nullptr, W,  FP(g_rmW), FP(g_rsW), FP(g_sdec), HF(g_WnT_h), HF(g_WnT_l));
    cudaEventRecord(ev_wn, s1);

    // ---- s2: Hebbian-Wr + rec GEMM + LN ----
    cudaStreamWaitEvent(s2, ev_as, 0);
    cudaStreamWaitEvent(s2, ev_ma, 0);
    mma_gemm<4,1,3><<<dim3(D/128, D/128), 256, SM1, s2>>>(
        HF(g_arsT), HF(g_maT), nullptr, BB, D,
        nullptr, nullptr, nullptr, Wr, FP(g_rmR), FP(g_rsR), FP(g_sdec), HF(g_WrT_h), HF(g_WrT_l));
    cudaStreamWaitEvent(s2, ev_pa, 0);
    mma_gemm<0,2,2><<<dim3(BB/128, D/128), 256, SM2, s2>>>(
        HF(g_pa), HF(g_WrT_h), HF(g_WrT_l), D, D,
        FP(g_rec), nullptr, nullptr, nullptr, nullptr, nullptr, nullptr, nullptr, nullptr);
    layernorm_kernel<<<BB, 256, 0, s2>>>(FP(g_rec), grec, brec, FP(g_recin));
    cudaEventRecord(ev_ri, s2);

    // ---- s0: JOIN + final GEMM + LN ----
    cudaStreamWaitEvent(0, ev_wn, 0);
    cudaStreamWaitEvent(0, ev_ri, 0);
    mma_gemm<3,2,2><<<dim3(BB/128, D/128), 256, SM2>>>(
        HF(g_x), HF(g_WnT_h), HF(g_WnT_l), D, D,
        FP(g_act), nullptr, FP(g_recin), nullptr, nullptr, nullptr, nullptr, nullptr, nullptr);
    layernorm_kernel<<<BB, 256>>>(FP(g_act), gact, bact, out);
}

// round 14
// speedup vs baseline: 1.0920x; 1.0920x over previous
#include <cuda_runtime.h>
#include <cuda_fp16.h>
#include <math.h>
#include <stdint.h>

#define D 4096
#define BB 512
#define N3 (3*D)
// kind::f16, fp16 inputs, fp32 accum, M=128, N=128
#define IDESC_F16 ((1u<<4)|(16u<<17)|(8u<<24))

#if defined(__CUDA_ARCH_FEAT_SM103_ALL) || defined(__CUDA_ARCH_FEAT_SM100_ALL) || \
    defined(__CUDA_ARCH_FEAT_SM101_ALL) || \
    (defined(__CUDA_ARCH_SPECIFIC__) && (__CUDA_ARCH_SPECIFIC__ >= 1000)) || \
    (defined(__CUDA_ARCH_FAMILY_SPECIFIC__) && (__CUDA_ARCH_FAMILY_SPECIFIC__ >= 1000))
#define TC_OK 1
#else
#define TC_OK 0
#endif

// ---------------- device scratch ----------------
__device__ __half g_pa[BB*D], g_x[BB*D], g_h[BB*D];
__device__ __half g_p1[(size_t)D*D];
__device__ __half g_p2[(size_t)N3*D];          // channel-permuted rows: c*D+j <- 3j+c
__device__ float  g_p2b[N3];
__device__ __half g_asT[(size_t)D*BB], g_arsT[(size_t)D*BB];
__device__ __half g_maT[(size_t)D*BB];
__device__ __half g_WnT_h[(size_t)D*D], g_WnT_l[(size_t)D*D];
__device__ __half g_WrT_h[(size_t)D*D], g_WrT_l[(size_t)D*D];
__device__ float g_nt[(size_t)BB*N3];
__device__ float g_rec[BB*D], g_recin[BB*D], g_act[BB*D];
__device__ float g_gsum[D], g_sdec[D], g_rmW[D], g_rsW[D], g_rmR[D], g_rsR[D];
__device__ float g_mPA[BB], g_sPA[BB], g_mPR[BB], g_sPR[BB];

// ---------------- helpers ----------------
__device__ __forceinline__ uint32_t s2u(const void* p) {
    uint32_t a;
    asm("{ .reg .u64 t; cvta.to.shared.u64 t, %1; cvt.u32.u64 %0, t; }" : "=r"(a) : "l"(p));
    return a;
}
__device__ __forceinline__ uint32_t sw128(uint32_t o) { return o ^ ((o >> 3) & 0x70); }
__device__ __forceinline__ void split2h(float v, __half& h, __half& l) {
    h = __float2half_rn(v);
    l = __float2half_rn(v - __half2float(h));
}
__device__ __forceinline__ float sigm(float x) { return 1.f / (1.f + expf(-x)); }

#if TC_OK
__device__ __forceinline__ void cp16(uint32_t d, const void* g) {
    asm volatile("cp.async.cg.shared.global [%0], [%1], 16;" :: "r"(d), "l"(g));
}
__device__ __forceinline__ uint64_t sdesc(uint32_t a) {
    return 0x4000404000010000ull | ((uint64_t)(a >> 4) & 0x3FFFull);
}
__device__ __forceinline__ void mma_f16(uint32_t d, uint64_t ad, uint64_t bd, uint32_t en) {
    asm volatile(
        "{\n\t.reg .pred p;\n\t"
        "setp.ne.u32 p, %5, 0;\n\t"
        "tcgen05.mma.cta_group::1.kind::f16 [%0], %1, %2, %3, {%4, %4, %4, %4}, p;\n\t}"
        :: "r"(d), "l"(ad), "l"(bd), "r"(IDESC_F16), "r"(0u), "r"(en) : "memory");
}
__device__ __forceinline__ void mma_commit(uint32_t mb) {
    asm volatile("tcgen05.commit.cta_group::1.mbarrier::arrive::one.shared::cluster.b64 [%0];"
                 :: "r"(mb) : "memory");
}
__device__ __forceinline__ void mbar_init(uint32_t mb, uint32_t cnt) {
    asm volatile("mbarrier.init.shared.b64 [%0], %1;" :: "r"(mb), "r"(cnt) : "memory");
}
__device__ __forceinline__ void mbar_wait(uint32_t mb, uint32_t par) {
    asm volatile(
        "{\n\t.reg .pred P;\nW%=:\n\t"
        "mbarrier.try_wait.parity.shared.b64 P, [%0], %1;\n\t"
        "@!P bra W%=;\n\t}"
        :: "r"(mb), "r"(par) : "memory");
}
// .noinc: deferred arrive CONSUMES one of the init-count arrivals (init=128 producers).
__device__ __forceinline__ void cp_arrive(uint32_t mb) {
    asm volatile("cp.async.mbarrier.arrive.noinc.shared::cta.b64 [%0];" :: "r"(mb) : "memory");
}
__device__ __forceinline__ void ldtm32(uint32_t* r, uint32_t a) {
    asm volatile(
        "tcgen05.ld.sync.aligned.32x32b.x32.b32 "
        "{%0,%1,%2,%3,%4,%5,%6,%7,%8,%9,%10,%11,%12,%13,%14,%15,"
        "%16,%17,%18,%19,%20,%21,%22,%23,%24,%25,%26,%27,%28,%29,%30,%31}, [%32];"
        : "=r"(r[0]),"=r"(r[1]),"=r"(r[2]),"=r"(r[3]),"=r"(r[4]),"=r"(r[5]),"=r"(r[6]),"=r"(r[7]),
          "=r"(r[8]),"=r"(r[9]),"=r"(r[10]),"=r"(r[11]),"=r"(r[12]),"=r"(r[13]),"=r"(r[14]),"=r"(r[15]),
          "=r"(r[16]),"=r"(r[17]),"=r"(r[18]),"=r"(r[19]),"=r"(r[20]),"=r"(r[21]),"=r"(r[22]),"=r"(r[23]),
          "=r"(r[24]),"=r"(r[25]),"=r"(r[26]),"=r"(r[27]),"=r"(r[28]),"=r"(r[29]),"=r"(r[30]),"=r"(r[31])
        : "r"(a));
}
#endif

// ---------------- GEMM: C[m,n] = sum_k A[m,k]*B[n,k]; A fp16; B = NBL fp16 panels ----------------
// Warp-specialized: warps 4-7 produce via cp.async (+mbarrier arrive.noinc), thread 0 issues MMAs.
// EPI: 0 fp32; 1 +bias relu -> fp16; 2 +bias fp32; 3 +addmat relu fp32; 4 Hebbian -> transposed hi/lo
template<int EPI, int NBL, int NST>
__global__ void __launch_bounds__(256)
mma_gemm(const __half* __restrict__ A,
         const __half* __restrict__ Bh, const __half* __restrict__ Bl,
         int K, int ldC, float* __restrict__ C,
         const float* __restrict__ bias, const float* __restrict__ addmat,
         const float* __restrict__ Wold, const float* __restrict__ rmax,
         const float* __restrict__ rsum, const float* __restrict__ sdec,
         __half* __restrict__ Oh, __half* __restrict__ Ol) {
    extern __shared__ char dsm[];
    const int tid = threadIdx.x;
    const int m0 = blockIdx.x * 128, n0 = blockIdx.y * 128;
    constexpr int NP = 1 + NBL;
    constexpr int STAGE = NP * 16384;

#if TC_OK
    __shared__ uint32_t s_tm;
    __shared__ __align__(8) uint64_t s_mbF[NST], s_mbE[NST];
    const int wid = tid >> 5, lid = tid & 31;
    uint32_t tile0 = (s2u(dsm) + 1023u) & ~1023u;
    uint32_t mbF[NST], mbE[NST];
#pragma unroll
    for (int s = 0; s < NST; s++) { mbF[s] = s2u(&s_mbF[s]); mbE[s] = s2u(&s_mbE[s]); }

    if (wid == 0) {
        asm volatile("tcgen05.alloc.cta_group::1.sync.aligned.shared::cta.b32 [%0], %1;"
                     :: "r"(s2u(&s_tm)), "r"(128u) : "memory");
        asm volatile("tcgen05.relinquish_alloc_permit.cta_group::1.sync.aligned;");
    }
    if (tid == 0)
        for (int s = 0; s < NST; s++) { mbar_init(mbF[s], 128); mbar_init(mbE[s], 1); }
    __syncthreads();
    const uint32_t tm = s_tm;
    const int NC = K >> 6;

    if (wid >= 4) {
        // ---------------- producer warps (128 threads) ----------------
        const int pt = tid - 128;
        const __half* srcs[3] = { A + (size_t)m0 * K, Bh + (size_t)n0 * K,
                                  NBL == 2 ? Bl + (size_t)n0 * K : nullptr };
        for (int i = 0; i < NC; i++) {
            const int s = i % NST;
            if (i >= NST) mbar_wait(mbE[s], ((i / NST) - 1) & 1);
            uint32_t base = tile0 + s * STAGE;
#pragma unroll
            for (int p = 0; p < NP; p++) {
                const __half* sp = srcs[p] + i * 64;
                uint32_t pb = base + p * 16384;
#pragma unroll
                for (int t = 0; t < 8; t++) {
                    int idx = pt + t * 128;
                    int r = idx >> 3, c = idx & 7;
                    cp16(pb + sw128(r * 128 + c * 16), sp + (size_t)r * K + c * 8);
                }
            }
            cp_arrive(mbF[s]);
        }
    } else if (tid == 0) {
        // ---------------- MMA issuer ----------------
        for (int i = 0; i < NC; i++) {
            const int s = i % NST;
            mbar_wait(mbF[s], (i / NST) & 1);
            asm volatile("fence.proxy.async.shared::cta;" ::: "memory");
            uint32_t base = tile0 + s * STAGE;
            uint64_t ad = sdesc(base);
            uint64_t bh = sdesc(base + 16384);
            uint64_t bl = sdesc(base + 32768);
#pragma unroll
            for (int s4 = 0; s4 < 4; s4++) {
                mma_f16(tm, ad + 2*s4, bh + 2*s4, (i > 0) | (s4 > 0));
                if (NBL == 2) mma_f16(tm, ad + 2*s4, bl + 2*s4, 1);
            }
            mma_commit(mbE[s]);
        }
        // last commit completion implies ALL prior MMAs complete
        mbar_wait(mbE[(NC - 1) % NST], ((NC - 1) / NST) & 1);
    }
    __syncthreads();
    asm volatile("tcgen05.fence::after_thread_sync;" ::: "memory");

    if (wid < 4) {
        const int m = m0 + wid * 32 + lid;
        float sd = 0.f, rm = 0.f, irs = 1.f;
        if (EPI == 4) { sd = sdec[m]; rm = rmax[m]; irs = 1.f / rsum[m]; }
#pragma unroll
        for (int cb = 0; cb < 4; cb++) {
            uint32_t rr[32];
            ldtm32(rr, tm + cb * 32);
            asm volatile("tcgen05.wait::ld.sync.aligned;" ::: "memory");
            const int nb = n0 + cb * 32;
            if (EPI == 0) {
                float4* c4 = (float4*)(C + (size_t)m * ldC + nb);
#pragma unroll
                for (int q = 0; q < 8; q++)
                    c4[q] = make_float4(__uint_as_float(rr[4*q]), __uint_as_float(rr[4*q+1]),
                                        __uint_as_float(rr[4*q+2]), __uint_as_float(rr[4*q+3]));
            } else if (EPI == 1) {
#pragma unroll
                for (int j = 0; j < 32; j += 2) {
                    float v0 = fmaxf(__uint_as_float(rr[j])   + bias[nb+j],   0.f);
                    float v1 = fmaxf(__uint_as_float(rr[j+1]) + bias[nb+j+1], 0.f);
                    *(__half2*)(Oh + (size_t)m * ldC + nb + j) = __floats2half2_rn(v0, v1);
                }
            } else if (EPI == 2) {
                float4* c4 = (float4*)(C + (size_t)m * ldC + nb);
#pragma unroll
                for (int q = 0; q < 8; q++)
                    c4[q] = make_float4(__uint_as_float(rr[4*q])   + bias[nb+4*q],
                                        __uint_as_float(rr[4*q+1]) + bias[nb+4*q+1],
                                        __uint_as_float(rr[4*q+2]) + bias[nb+4*q+2],
                                        __uint_as_float(rr[4*q+3]) + bias[nb+4*q+3]);
            } else if (EPI == 3) {
                const float4* a4 = (const float4*)(addmat + (size_t)m * ldC + nb);
                float4* c4 = (float4*)(C + (size_t)m * ldC + nb);
#pragma unroll
                for (int q = 0; q < 8; q++) {
                    float4 a = a4[q];
                    c4[q] = make_float4(fmaxf(__uint_as_float(rr[4*q])   + a.x, 0.f),
                                        fmaxf(__uint_as_float(rr[4*q+1]) + a.y, 0.f),
                                        fmaxf(__uint_as_float(rr[4*q+2]) + a.z, 0.f),
                                        fmaxf(__uint_as_float(rr[4*q+3]) + a.w, 0.f));
                }
            } else {
                const float4* w4 = (const float4*)(Wold + (size_t)m * D + nb);
#pragma unroll
                for (int q = 0; q < 8; q++) {
                    float4 w = w4[q];
                    float wv[4] = { w.x, w.y, w.z, w.w };
#pragma unroll
                    for (int e = 0; e < 4; e++) {
                        int j = 4*q + e;
                        float p = expf(wv[e] - rm) * irs;
                        float o = wv[e] + p * (__uint_as_float(rr[j]) * (1.0f/BB)) - sd * wv[e];
                        __half hh, ll;
                        split2h(o, hh, ll);
                        Oh[(size_t)(nb + j) * D + m] = hh;
                        Ol[(size_t)(nb + j) * D + m] = ll;
                    }
                }
            }
        }
    }
    __syncthreads();
    if (wid == 0)
        asm volatile("tcgen05.dealloc.cta_group::1.sync.aligned.b32 %0, %1;" :: "r"(tm), "r"(128u));

#else  // ---------- generic-target fallback ----------
    float* As = (float*)dsm;
    float* Bs = As + 16 * 132;
    const int tx = tid & 15, ty = tid >> 4;
    float acc[8][8];
#pragma unroll
    for (int i = 0; i < 8; i++)
#pragma unroll
        for (int j = 0; j < 8; j++) acc[i][j] = 0.f;
    for (int k0 = 0; k0 < K; k0 += 16) {
#pragma unroll
        for (int e = 0; e < 8; e++) {
            int idx = tid + e * 256;
            int r = idx >> 4, k = idx & 15;
            size_t ai = (size_t)(m0 + r) * K + k0 + k;
            size_t bi = (size_t)(n0 + r) * K + k0 + k;
            As[k * 132 + r] = __half2float(A[ai]);
            float bv = __half2float(Bh[bi]);
            if (NBL == 2) bv += __half2float(Bl[bi]);
            Bs[k * 132 + r] = bv;
        }
        __syncthreads();
#pragma unroll
        for (int kk = 0; kk < 16; kk++) {
            float a[8], b[8];
#pragma unroll
            for (int i = 0; i < 8; i++) a[i] = As[kk * 132 + ty * 8 + i];
#pragma unroll
            for (int j = 0; j < 8; j++) b[j] = Bs[kk * 132 + tx * 8 + j];
#pragma unroll
            for (int i = 0; i < 8; i++)
#pragma unroll
                for (int j = 0; j < 8; j++) acc[i][j] = fmaf(a[i], b[j], acc[i][j]);
        }
        __syncthreads();
    }
#pragma unroll
    for (int i = 0; i < 8; i++) {
        int m = m0 + ty * 8 + i;
        float sd = 0.f, rm = 0.f, irs = 1.f;
        if (EPI == 4) { sd = sdec[m]; rm = rmax[m]; irs = 1.f / rsum[m]; }
#pragma unroll
        for (int j = 0; j < 8; j++) {
            int n = n0 + tx * 8 + j;
            float v = acc[i][j];
            if (EPI == 0) C[(size_t)m * ldC + n] = v;
            else if (EPI == 1) Oh[(size_t)m * ldC + n] = __float2half_rn(fmaxf(v + bias[n], 0.f));
            else if (EPI == 2) C[(size_t)m * ldC + n] = v + bias[n];
            else if (EPI == 3) C[(size_t)m * ldC + n] = fmaxf(v + addmat[(size_t)m * ldC + n], 0.f);
            else {
                float w = Wold[(size_t)m * D + n];
                float p = expf(w - rm) * irs;
                float o = w + p * (v * (1.0f/BB)) - sd * w;
                __half hh, ll; split2h(o, hh, ll);
                Oh[(size_t)n * D + m] = hh; Ol[(size_t)n * D + m] = ll;
            }
        }
    }
#endif
}

// ---------------- block reduce + elementwise ----------------
__device__ __forceinline__ float blk_reduce(float v, bool do_max) {
    __shared__ float sh[32];
    int lane = threadIdx.x & 31, w = threadIdx.x >> 5;
#pragma unroll
    for (int o = 16; o; o >>= 1) {
        float t = __shfl_xor_sync(0xffffffffu, v, o);
        v = do_max ? fmaxf(v, t) : v + t;
    }
    if (lane == 0) sh[w] = v;
    __syncthreads();
    if (w == 0) {
        v = (lane < (int)(blockDim.x >> 5)) ? sh[lane] : (do_max ? -INFINITY : 0.f);
#pragma unroll
        for (int o = 16; o; o >>= 1) {
            float t = __shfl_xor_sync(0xffffffffu, v, o);
            v = do_max ? fmaxf(v, t) : v + t;
        }
        if (lane == 0) sh[0] = v;
    }
    __syncthreads();
    float r = sh[0];
    __syncthreads();
    return r;
}

__global__ void row_stats_kernel(const float* __restrict__ src,
                                 float* __restrict__ rmax, float* __restrict__ rsum) {
    int row = blockIdx.x;
    const float* x = src + (size_t)row * D;
    float m = -INFINITY;
    for (int i = threadIdx.x; i < D; i += blockDim.x) m = fmaxf(m, x[i]);
    m = blk_reduce(m, true);
    float s = 0.f;
    for (int i = threadIdx.x; i < D; i += blockDim.x) s += expf(x[i] - m);
    s = blk_reduce(s, false);
    if (threadIdx.x == 0) { rmax[row] = m; rsum[row] = s; }
}

__global__ void softmax_tn_kernel(const float* __restrict__ src,
                                  const float* __restrict__ rm, const float* __restrict__ rs,
                                  __half* __restrict__ dst) {
    __shared__ float tile[32][33];
    __shared__ float tm[32], ts[32];
    int i0 = blockIdx.x * 32, b0 = blockIdx.y * 32;
    int tx = threadIdx.x & 31, ty = threadIdx.x >> 5;
    if (threadIdx.x < 32) { tm[threadIdx.x] = rm[b0 + threadIdx.x]; ts[threadIdx.x] = 1.f / rs[b0 + threadIdx.x]; }
    __syncthreads();
#pragma unroll
    for (int r = ty; r < 32; r += 8)
        tile[r][tx] = src[(size_t)(b0 + r) * D + i0 + tx];
    __syncthreads();
#pragma unroll
    for (int r = ty; r < 32; r += 8)
        dst[(size_t)(i0 + r) * BB + b0 + tx] = __float2half_rn(expf(tile[tx][r] - tm[tx]) * ts[tx]);
}

__global__ void layernorm_kernel(const float* __restrict__ src,
                                 const float* __restrict__ g, const float* __restrict__ b,
                                 float* __restrict__ dst) {
    int row = blockIdx.x;
    const float* x = src + (size_t)row * D;
    float s = 0.f, s2 = 0.f;
    for (int i = threadIdx.x; i < D; i += blockDim.x) { float v = x[i]; s += v; s2 += v * v; }
    s = blk_reduce(s, false);
    s2 = blk_reduce(s2, false);
    float mean = s * (1.f / D);
    float rstd = rsqrtf(s2 * (1.f / D) - mean * mean + 1e-5f);
    for (int i = threadIdx.x; i < D; i += blockDim.x)
        dst[(size_t)row * D + i] = (x[i] - mean) * rstd * g[i] + b[i];
}

__global__ void zero_kernel(float* p, int n) {
    int i = blockIdx.x * blockDim.x + threadIdx.x;
    if (i < n) p[i] = 0.f;
}

__global__ void neuromod_t(const float* __restrict__ nt,
                           const float* __restrict__ dopamine,
                           const float* __restrict__ serotonin,
                           const float* __restrict__ gaba,
                           const float* __restrict__ alpha,
                           __half* __restrict__ maT, float* __restrict__ gsum) {
    __shared__ float tile[64][33];
    int j0 = blockIdx.x * 32, b0 = blockIdx.y * 64;
    int tx = threadIdx.x & 31, ty = threadIdx.x >> 5;
    int j = j0 + tx;
    float a = alpha[j];
    float gs = 0.f;
    for (int bb = ty; bb < 64; bb += 8) {
        int b = b0 + bb;
        const float* p = nt + (size_t)b * N3;
        float pd = p[j], ps = p[D + j], pg = p[2*D + j];
        float inv = 1.f / fmaxf(ps, 1e-6f);
        size_t bi = (size_t)b * D + j;
        float dop = tanhf(dopamine[bi] + pd * inv);
        float ser = sigm(serotonin[bi] + ps);
        gs += sigm(gaba[bi] + pg * inv);
        tile[bb][tx] = a * dop * ser;
    }
    atomicAdd(&gsum[j], gs);
    __syncthreads();
    int c = threadIdx.x & 63, jy = threadIdx.x >> 6;
#pragma unroll
    for (int jj = jy; jj < 32; jj += 4)
        maT[(size_t)(j0 + jj) * BB + b0 + c] = __float2half_rn(tile[c][jj]);
}

__global__ void sdecay_kernel(const float* __restrict__ gsum,
                              const float* __restrict__ decay, float* __restrict__ sdec) {
    int j = blockIdx.x * blockDim.x + threadIdx.x;
    sdec[j] = decay[j] * sigm(gsum[j] * (1.f / BB));
}

__global__ void cvt_kernel(const float4* __restrict__ src, __half* __restrict__ dst, size_t n4) {
    size_t i = (size_t)blockIdx.x * blockDim.x + threadIdx.x;
    if (i >= n4) return;
    float4 v = src[i];
    ((__half2*)dst)[2*i]   = __floats2half2_rn(v.x, v.y);
    ((__half2*)dst)[2*i+1] = __floats2half2_rn(v.z, v.w);
}

__global__ void cvt_permute_kernel(const float* __restrict__ src, __half* __restrict__ dst) {
    int r = blockIdx.x;
    int c = r % 3, j = r / 3;
    const float4* s4 = (const float4*)(src + (size_t)r * D);
    __half2* d2 = (__half2*)(dst + (size_t)(c * D + j) * D);
    for (int i = threadIdx.x; i < D / 4; i += blockDim.x) {
        float4 v = s4[i];
        d2[2*i]   = __floats2half2_rn(v.x, v.y);
        d2[2*i+1] = __floats2half2_rn(v.z, v.w);
    }
}

__global__ void permute_bias_kernel(const float* __restrict__ src, float* __restrict__ dst) {
    int r = blockIdx.x * blockDim.x + threadIdx.x;
    if (r < N3) dst[(r % 3) * D + r / 3] = src[r];
}

// ---------------- host ----------------
template<typename T>
static void* sym_addr(T& sym) { void* p = nullptr; cudaGetSymbolAddress(&p, sym); return p; }
#define HF(sym) ((__half*)sym_addr(sym))
#define FP(sym) ((float*)sym_addr(sym))

extern "C" void kernel_launch(void* const* d_in, const int* in_sizes, int n_in,
                              void* d_out, int out_size) {
    const float* x        = (const float*)d_in[0];
    const float* prev_act = (const float*)d_in[1];
    const float* prev_rec = (const float*)d_in[2];
    const float* dopamine = (const float*)d_in[3];
    const float* serotonin= (const float*)d_in[4];
    const float* gaba     = (const float*)d_in[5];
    const float* W        = (const float*)d_in[6];
    const float* Wr       = (const float*)d_in[7];
    const float* alpha    = (const float*)d_in[8];
    const float* decay    = (const float*)d_in[9];
    const float* gact     = (const float*)d_in[10];
    const float* bact     = (const float*)d_in[11];
    const float* grec     = (const float*)d_in[12];
    const float* brec     = (const float*)d_in[13];
    const float* p1w      = (const float*)d_in[14];
    const float* p1b      = (const float*)d_in[15];
    const float* p2w      = (const float*)d_in[16];
    const float* p2b      = (const float*)d_in[17];
    float* out = (float*)d_out;

    const int SM1 = 3 * 32768 + 1024;   // NBL=1, NST=3
    const int SM2 = 2 * 49152 + 1024;   // NBL=2, NST=2

    static cudaStream_t s1, s2;
    static cudaEvent_t ev_root, ev_pa, ev_as, ev_p2, ev_sw, ev_ma, ev_wn, ev_ri;
    static bool init_done = false;
    if (!init_done) {
        cudaStreamCreateWithFlags(&s1, cudaStreamNonBlocking);
        cudaStreamCreateWithFlags(&s2, cudaStreamNonBlocking);
        cudaEventCreateWithFlags(&ev_root, cudaEventDisableTiming);
        cudaEventCreateWithFlags(&ev_pa, cudaEventDisableTiming);
        cudaEventCreateWithFlags(&ev_as, cudaEventDisableTiming);
        cudaEventCreateWithFlags(&ev_p2, cudaEventDisableTiming);
        cudaEventCreateWithFlags(&ev_sw, cudaEventDisableTiming);
        cudaEventCreateWithFlags(&ev_ma, cudaEventDisableTiming);
        cudaEventCreateWithFlags(&ev_wn, cudaEventDisableTiming);
        cudaEventCreateWithFlags(&ev_ri, cudaEventDisableTiming);
        cudaFuncSetAttribute((const void*)mma_gemm<1,1,3>, cudaFuncAttributeMaxDynamicSharedMemorySize, SM1);
        cudaFuncSetAttribute((const void*)mma_gemm<2,1,3>, cudaFuncAttributeMaxDynamicSharedMemorySize, SM1);
        cudaFuncSetAttribute((const void*)mma_gemm<4,1,3>, cudaFuncAttributeMaxDynamicSharedMemorySize, SM1);
        cudaFuncSetAttribute((const void*)mma_gemm<0,2,2>, cudaFuncAttributeMaxDynamicSharedMemorySize, SM2);
        cudaFuncSetAttribute((const void*)mma_gemm<3,2,2>, cudaFuncAttributeMaxDynamicSharedMemorySize, SM2);
        init_done = true;
    }

    // ---- FORK: side streams join capture via origin-stream event FIRST ----
    cudaEventRecord(ev_root, 0);
    cudaStreamWaitEvent(s1, ev_root, 0);
    cudaStreamWaitEvent(s2, ev_root, 0);

    // ---- s0: input converts ----
    cvt_kernel<<<(BB*D/4 + 255)/256, 256>>>((const float4*)prev_act, HF(g_pa), BB*D/4);
    cvt_kernel<<<(BB*D/4 + 255)/256, 256>>>((const float4*)x,        HF(g_x),  BB*D/4);
    cudaEventRecord(ev_pa, 0);

    // ---- s1: p1 convert -> GEMM1 ----
    cvt_kernel<<<((size_t)D*D/4 + 255)/256, 256, 0, s1>>>((const float4*)p1w, HF(g_p1), (size_t)D*D/4);
    cudaStreamWaitEvent(s1, ev_pa, 0);
    mma_gemm<1,1,3><<<dim3(BB/128, D/128), 256, SM1, s1>>>(
        HF(g_pa), HF(g_p1), nullptr, D, D,
        nullptr, p1b, nullptr, nullptr, nullptr, nullptr, nullptr, HF(g_h), nullptr);

    // ---- s2: p2 convert + W row stats ----
    cvt_permute_kernel<<<N3, 256, 0, s2>>>(p2w, HF(g_p2));
    permute_bias_kernel<<<(N3 + 255)/256, 256, 0, s2>>>(p2b, FP(g_p2b));
    cudaEventRecord(ev_p2, s2);
    row_stats_kernel<<<D, 256, 0, s2>>>(W,  FP(g_rmW), FP(g_rsW));
    cudaEventRecord(ev_sw, s2);
    row_stats_kernel<<<D, 256, 0, s2>>>(Wr, FP(g_rmR), FP(g_rsR));

    // ---- s0: transposed softmaxes ----
    row_stats_kernel<<<BB, 256>>>(prev_act, FP(g_mPA), FP(g_sPA));
    softmax_tn_kernel<<<dim3(D/32, BB/32), 256>>>(prev_act, FP(g_mPA), FP(g_sPA), HF(g_asT));
    row_stats_kernel<<<BB, 256>>>(prev_rec, FP(g_mPR), FP(g_sPR));
    softmax_tn_kernel<<<dim3(D/32, BB/32), 256>>>(prev_rec, FP(g_mPR), FP(g_sPR), HF(g_arsT));
    cudaEventRecord(ev_as, 0);

    // ---- s1: GEMM2 + neuromod + Hebbian-W ----
    cudaStreamWaitEvent(s1, ev_p2, 0);
    mma_gemm<2,1,3><<<dim3(BB/128, N3/128), 256, SM1, s1>>>(
        HF(g_h), HF(g_p2), nullptr, D, N3,
        FP(g_nt), FP(g_p2b), nullptr, nullptr, nullptr, nullptr, nullptr, nullptr, nullptr);
    zero_kernel<<<D/256, 256, 0, s1>>>(FP(g_gsum), D);
    neuromod_t<<<dim3(D/32, BB/64), 256, 0, s1>>>(FP(g_nt), dopamine, serotonin, gaba, alpha,
                                                  HF(g_maT), FP(g_gsum));
    sdecay_kernel<<<D/256, 256, 0, s1>>>(FP(g_gsum), decay, FP(g_sdec));
    cudaEventRecord(ev_ma, s1);
    cudaStreamWaitEvent(s1, ev_as, 0);
    cudaStreamWaitEvent(s1, ev_sw, 0);
    mma_gemm<4,1,3><<<dim3(D/128, D/128), 256, SM1, s1>>>(
        HF(g_asT), HF(g_maT), nullptr, BB, D,
        nullptr, nullptr, nullptr, W,  FP(g_rmW), FP(g_rsW), FP(g_sdec), HF(g_WnT_h), HF(g_WnT_l));
    cudaEventRecord(ev_wn, s1);

    // ---- s2: Hebbian-Wr + rec GEMM + LN ----
    cudaStreamWaitEvent(s2, ev_as, 0);
    cudaStreamWaitEvent(s2, ev_ma, 0);
    mma_gemm<4,1,3><<<dim3(D/128, D/128), 256, SM1, s2>>>(
        HF(g_arsT), HF(g_maT), nullptr, BB, D,
        nullptr, nullptr, nullptr, Wr, FP(g_rmR), FP(g_rsR), FP(g_sdec), HF(g_WrT_h), HF(g_WrT_l));
    cudaStreamWaitEvent(s2, ev_pa, 0);
    mma_gemm<0,2,2><<<dim3(BB/128, D/128), 256, SM2, s2>>>(
        HF(g_pa), HF(g_WrT_h), HF(g_WrT_l), D, D,
        FP(g_rec), nullptr, nullptr, nullptr, nullptr, nullptr, nullptr, nullptr, nullptr);
    layernorm_kernel<<<BB, 256, 0, s2>>>(FP(g_rec), grec, brec, FP(g_recin));
    cudaEventRecord(ev_ri, s2);

    // ---- s0: JOIN + final GEMM + LN ----
    cudaStreamWaitEvent(0, ev_wn, 0);
    cudaStreamWaitEvent(0, ev_ri, 0);
    mma_gemm<3,2,2><<<dim3(BB/128, D/128), 256, SM2>>>(
        HF(g_x), HF(g_WnT_h), HF(g_WnT_l), D, D,
        FP(g_act), nullptr, FP(g_recin), nullptr, nullptr, nullptr, nullptr, nullptr, nullptr);
    layernorm_kernel<<<BB, 256>>>(FP(g_act), gact, bact, out);
}